// round 6
// baseline (speedup 1.0000x reference)
#include <cuda_runtime.h>
#include <cuda_bf16.h>

#define TLEN 2048
#define H 20
typedef unsigned long long ull;

// ---- packed f32x2 helpers ----
__device__ __forceinline__ ull pk(float lo, float hi) {
    ull r; asm("mov.b64 %0, {%1, %2};" : "=l"(r) : "f"(lo), "f"(hi)); return r;
}
__device__ __forceinline__ float2 upk(ull v) {
    float2 f; asm("mov.b64 {%0, %1}, %2;" : "=f"(f.x), "=f"(f.y) : "l"(v)); return f;
}
__device__ __forceinline__ ull fma2(ull a, ull b, ull c) {
    ull d; asm("fma.rn.f32x2 %0, %1, %2, %3;" : "=l"(d) : "l"(a), "l"(b), "l"(c)); return d;
}

// z pre-scaled by 2*log2(e): tanh(a) = 1 - 2/(exp2(z) + 1).
__device__ __forceinline__ float tanh_ps(float z) {
    float e; asm("ex2.approx.f32 %0, %1;" : "=f"(e) : "f"(z));
    float r; asm("rcp.approx.f32 %0, %1;" : "=f"(r) : "f"(e + 1.0f));
    return fmaf(-2.0f, r, 1.0f);
}
__device__ __forceinline__ float sigmoid1(float z) {
    float e; asm("ex2.approx.f32 %0, %1;" : "=f"(e) : "f"(z * -1.4426950408889634f));
    float r; asm("rcp.approx.f32 %0, %1;" : "=f"(r) : "f"(e + 1.0f));
    return r;
}

// Pair permutation over the K dimension (dot products are order-free):
//   j in [0,8): pair (5*(j>>1) + 2*(j&1), +1)  -> thread q OWNS pairs 2q, 2q+1
//   j = 8: rows (4, 9)    j = 9: rows (14, 19) -> straddle pairs, scalar halves
__device__ __forceinline__ int pairA(int j) {
    if (j == 8) return 4;
    if (j == 9) return 14;
    return 5 * (j >> 1) + 2 * (j & 1);
}
__device__ __forceinline__ int pairB(int j) {
    if (j == 8) return 9;
    if (j == 9) return 19;
    return 5 * (j >> 1) + 2 * (j & 1) + 1;
}

// 4 threads per batch (quad). Thread q owns hidden rows [5q, 5q+5).
// Weights packed over K under the permutation above: 8 pairs/row in registers
// (80 regs), pairs j=8,9 in warp-broadcast smem (one LDS.128 per row).
// h-exchange: STS pairs -> __syncwarp -> 10x LDS.64 straight into packed
// register pairs (replaces 20 SHFL + 10 pack-MOVs of R5). Double-buffered
// smem h so ONE syncwarp per step suffices.
// launch_bounds(32,14) -> 146-reg cap -> 14 blocks/SM -> single balanced wave.
__global__ void __launch_bounds__(32, 14) rnn_kernel(
    const float* __restrict__ x,      // [B, TLEN]
    const float* __restrict__ W_ih,   // [H]
    const float* __restrict__ W_hh,   // [H, H]
    const float* __restrict__ b_ih,   // [H]
    const float* __restrict__ b_hh,   // [H]
    const float* __restrict__ W_fc,   // [H]
    const float* __restrict__ b_fc,   // [1]
    float* __restrict__ out)          // [B]
{
    __shared__ float sW[H][H];                        // scaled W_hh
    __shared__ __align__(16) ulonglong2 sTailW[5][4]; // [i][q] = pairs j=8,9 of row 5q+i
    __shared__ ull hbuf[2][10][8];                    // [buf][pair][batch8]
    __shared__ float sWih[H], sPre[H], sWfc[H];
    __shared__ float sBfc;

    const int tid = threadIdx.x;
    const float SC = 2.8853900817779268f;             // 2*log2(e)

    for (int i = tid; i < H * H; i += 32) sW[i / H][i % H] = W_hh[i] * SC;
    if (tid < H) {
        sWih[tid] = W_ih[tid] * SC;
        sPre[tid] = (b_ih[tid] + b_hh[tid]) * SC;
        sWfc[tid] = W_fc[tid];
    }
    if (tid == 0) sBfc = b_fc[0];
    __syncthreads();
    // tail weight pairs (cols {4,9} and {14,19}) per row, quad-indexed
    for (int idx = tid; idx < 5 * 4; idx += 32) {
        int qq = idx & 3, ii = idx >> 2;
        const float* row = sW[5 * qq + ii];
        ulonglong2 v;
        v.x = pk(row[4],  row[9]);
        v.y = pk(row[14], row[19]);
        sTailW[ii][qq] = v;
    }
    __syncthreads();

    const int q  = tid & 3;
    const int b8 = tid >> 2;
    const int batch = blockIdx.x * 8 + b8;

    // register weights: rows 5q..5q+4, pairs j=0..7 (permuted K pairs)
    ull wk[5][8], pre2[5];
    float wih[5];
    #pragma unroll
    for (int i = 0; i < 5; i++) {
        const int r = 5 * q + i;
        #pragma unroll
        for (int j = 0; j < 8; j++)
            wk[i][j] = pk(sW[r][pairA(j)], sW[r][pairB(j)]);
        wih[i]  = sWih[r];
        pre2[i] = pk(sPre[r], 0.0f);
    }

    ull hp[10];
    #pragma unroll
    for (int j = 0; j < 10; j++) hp[j] = 0ull;

    const float* xp = x + (size_t)batch * TLEN;
    float4 xv = *(const float4*)xp;

    for (int t = 0; t < TLEN; t += 4) {
        float4 xn;
        if (t + 4 < TLEN) xn = *(const float4*)(xp + t + 4);
        const float xs[4] = {xv.x, xv.y, xv.z, xv.w};

        #pragma unroll
        for (int s = 0; s < 4; s++) {
            const int buf = s & 1;
            float m[5];
            #pragma unroll
            for (int i = 0; i < 5; i++) {
                ull acc = fma2(wk[i][0], hp[0], pre2[i]);
                #pragma unroll
                for (int j = 1; j < 8; j++)
                    acc = fma2(wk[i][j], hp[j], acc);
                ulonglong2 tw = sTailW[i][q];      // broadcast LDS.128
                acc = fma2(tw.x, hp[8], acc);
                acc = fma2(tw.y, hp[9], acc);
                float2 f = upk(acc);
                m[i] = tanh_ps(fmaf(xs[s], wih[i], f.x + f.y));
            }
            // quad h-exchange through smem (pairs land pre-packed)
            hbuf[buf][2 * q][b8]     = pk(m[0], m[1]);
            hbuf[buf][2 * q + 1][b8] = pk(m[2], m[3]);
            ((float*)&hbuf[buf][8 + (q >> 1)][b8])[q & 1] = m[4];
            __syncwarp();
            #pragma unroll
            for (int j = 0; j < 10; j++) hp[j] = hbuf[buf][j][b8];  // LDS.64
        }
        xv = xn;
    }

    if (q == 0) {
        ull acc = pk(sBfc, 0.0f);
        #pragma unroll
        for (int j = 0; j < 10; j++)
            acc = fma2(hp[j], pk(sWfc[pairA(j)], sWfc[pairB(j)]), acc);
        float2 f = upk(acc);
        out[batch] = sigmoid1(f.x + f.y);
    }
}

extern "C" void kernel_launch(void* const* d_in, const int* in_sizes, int n_in,
                              void* d_out, int out_size) {
    const float* x    = (const float*)d_in[0];
    const float* W_ih = (const float*)d_in[1];
    const float* W_hh = (const float*)d_in[2];
    const float* b_ih = (const float*)d_in[3];
    const float* b_hh = (const float*)d_in[4];
    const float* W_fc = (const float*)d_in[5];
    const float* b_fc = (const float*)d_in[6];
    float* out = (float*)d_out;

    const int B = in_sizes[0] / TLEN;   // 16384
    const int blocks = B / 8;           // 2048 blocks x 32 threads
    rnn_kernel<<<blocks, 32>>>(x, W_ih, W_hh, b_ih, b_hh, W_fc, b_fc, out);
}

// round 7
// speedup vs baseline: 1.0706x; 1.0706x over previous
#include <cuda_runtime.h>
#include <cuda_bf16.h>

#define TLEN 2048
#define H 20
typedef unsigned long long ull;

// ---- packed f32x2 helpers ----
__device__ __forceinline__ ull pk(float lo, float hi) {
    ull r; asm("mov.b64 %0, {%1, %2};" : "=l"(r) : "f"(lo), "f"(hi)); return r;
}
__device__ __forceinline__ float2 upk(ull v) {
    float2 f; asm("mov.b64 {%0, %1}, %2;" : "=f"(f.x), "=f"(f.y) : "l"(v)); return f;
}
__device__ __forceinline__ ull fma2(ull a, ull b, ull c) {
    ull d; asm("fma.rn.f32x2 %0, %1, %2, %3;" : "=l"(d) : "l"(a), "l"(b), "l"(c)); return d;
}

// z pre-scaled by 2*log2(e): tanh(a) = 1 - 2/(exp2(z) + 1).
__device__ __forceinline__ float tanh_ps(float z) {
    float e; asm("ex2.approx.f32 %0, %1;" : "=f"(e) : "f"(z));
    float r; asm("rcp.approx.f32 %0, %1;" : "=f"(r) : "f"(e + 1.0f));
    return fmaf(-2.0f, r, 1.0f);
}
__device__ __forceinline__ float sigmoid1(float z) {
    float e; asm("ex2.approx.f32 %0, %1;" : "=f"(e) : "f"(z * -1.4426950408889634f));
    float r; asm("rcp.approx.f32 %0, %1;" : "=f"(r) : "f"(e + 1.0f));
    return r;
}

// K-pair permutation (dot products are order-free):
//   j in [0,8): pair (5*(j>>1) + 2*(j&1), +1)  -> thread q OWNS pairs 2q, 2q+1
//   j = 8: rows (4, 9)    j = 9: rows (14, 19) -> straddle pairs
__device__ __forceinline__ int pairA(int j) {
    if (j == 8) return 4;
    if (j == 9) return 14;
    return 5 * (j >> 1) + 2 * (j & 1);
}
__device__ __forceinline__ int pairB(int j) {
    if (j == 8) return 9;
    if (j == 9) return 19;
    return 5 * (j >> 1) + 2 * (j & 1) + 1;
}

// 4 threads per batch (quad). Thread q owns hidden rows [5q, 5q+5).
// ALL 10 packed weight pairs per row register-resident (100 regs): the inner
// loop has ZERO weight loads. h-exchange through double-buffered smem:
// 2x STS.64 + STS.32 + one __syncwarp + 10x LDS.64 landing directly in the
// packed hp[] register pairs (replaces R5's 20 SHFL + ~30 pack MOVs).
// BARE launch bounds: R4/R6 both proved that any reg cap (ptxas picks 128)
// spills the weight array to local memory and dominates runtime. Natural
// ~160 regs -> 12 blocks/SM, 2048 blocks, ~15% second-wave tail.
__global__ void __launch_bounds__(32) rnn_kernel(
    const float* __restrict__ x,      // [B, TLEN]
    const float* __restrict__ W_ih,   // [H]
    const float* __restrict__ W_hh,   // [H, H]
    const float* __restrict__ b_ih,   // [H]
    const float* __restrict__ b_hh,   // [H]
    const float* __restrict__ W_fc,   // [H]
    const float* __restrict__ b_fc,   // [1]
    float* __restrict__ out)          // [B]
{
    __shared__ float sW[H][H];        // scaled W_hh
    __shared__ ull hbuf[2][10][8];    // [buf][pair][batch8] -- 64B per [buf][pair]
    __shared__ float sWih[H], sPre[H], sWfc[H];
    __shared__ float sBfc;

    const int tid = threadIdx.x;
    const float SC = 2.8853900817779268f;   // 2*log2(e)

    for (int i = tid; i < H * H; i += 32) sW[i / H][i % H] = W_hh[i] * SC;
    if (tid < H) {
        sWih[tid] = W_ih[tid] * SC;
        sPre[tid] = (b_ih[tid] + b_hh[tid]) * SC;
        sWfc[tid] = W_fc[tid];
    }
    if (tid == 0) sBfc = b_fc[0];
    __syncthreads();

    const int q  = tid & 3;
    const int b8 = tid >> 2;
    const int batch = blockIdx.x * 8 + b8;

    // register weights: rows 5q..5q+4, all 10 permuted K-pairs
    ull wk[5][10], pre2[5];
    float wih[5];
    #pragma unroll
    for (int i = 0; i < 5; i++) {
        const int r = 5 * q + i;
        #pragma unroll
        for (int j = 0; j < 10; j++)
            wk[i][j] = pk(sW[r][pairA(j)], sW[r][pairB(j)]);
        wih[i]  = sWih[r];
        pre2[i] = pk(sPre[r], 0.0f);
    }

    ull hp[10];
    #pragma unroll
    for (int j = 0; j < 10; j++) hp[j] = 0ull;

    const float* xp = x + (size_t)batch * TLEN;

    for (int t = 0; t < TLEN; t += 4) {
        const float4 xv = *(const float4*)(xp + t);   // LDG.128, hidden by warps
        const float xs[4] = {xv.x, xv.y, xv.z, xv.w};

        #pragma unroll
        for (int s = 0; s < 4; s++) {
            const int buf = s & 1;
            float m[5];
            #pragma unroll
            for (int i = 0; i < 5; i++) {
                ull acc = fma2(wk[i][0], hp[0], pre2[i]);
                #pragma unroll
                for (int j = 1; j < 10; j++)
                    acc = fma2(wk[i][j], hp[j], acc);
                float2 f = upk(acc);
                m[i] = tanh_ps(fmaf(xs[s], wih[i], f.x + f.y));
            }
            // quad h-exchange through smem: thread q owns pairs 2q,2q+1 whole,
            // plus one scalar half of a straddle pair.
            hbuf[buf][2 * q][b8]     = pk(m[0], m[1]);   // STS.64
            hbuf[buf][2 * q + 1][b8] = pk(m[2], m[3]);   // STS.64
            ((float*)&hbuf[buf][8 + (q >> 1)][b8])[q & 1] = m[4];  // STS.32
            __syncwarp();
            #pragma unroll
            for (int j = 0; j < 10; j++) hp[j] = hbuf[buf][j][b8]; // LDS.64 -> pair
        }
    }

    if (q == 0) {
        ull acc = pk(sBfc, 0.0f);
        #pragma unroll
        for (int j = 0; j < 10; j++)
            acc = fma2(hp[j], pk(sWfc[pairA(j)], sWfc[pairB(j)]), acc);
        float2 f = upk(acc);
        out[batch] = sigmoid1(f.x + f.y);
    }
}

extern "C" void kernel_launch(void* const* d_in, const int* in_sizes, int n_in,
                              void* d_out, int out_size) {
    const float* x    = (const float*)d_in[0];
    const float* W_ih = (const float*)d_in[1];
    const float* W_hh = (const float*)d_in[2];
    const float* b_ih = (const float*)d_in[3];
    const float* b_hh = (const float*)d_in[4];
    const float* W_fc = (const float*)d_in[5];
    const float* b_fc = (const float*)d_in[6];
    float* out = (float*)d_out;

    const int B = in_sizes[0] / TLEN;   // 16384
    const int blocks = B / 8;           // 2048 blocks x 32 threads (4 thr/batch)
    rnn_kernel<<<blocks, 32>>>(x, W_ih, W_hh, b_ih, b_hh, W_fc, b_fc, out);
}

// round 8
// speedup vs baseline: 1.4095x; 1.3165x over previous
#include <cuda_runtime.h>
#include <cuda_bf16.h>

#define TLEN 2048
#define H 20
typedef unsigned long long ull;

// ---- packed f32x2 helpers ----
__device__ __forceinline__ ull pk(float lo, float hi) {
    ull r; asm("mov.b64 %0, {%1, %2};" : "=l"(r) : "f"(lo), "f"(hi)); return r;
}
__device__ __forceinline__ float2 upk(ull v) {
    float2 f; asm("mov.b64 {%0, %1}, %2;" : "=f"(f.x), "=f"(f.y) : "l"(v)); return f;
}
__device__ __forceinline__ ull fma2(ull a, ull b, ull c) {
    ull d; asm("fma.rn.f32x2 %0, %1, %2, %3;" : "=l"(d) : "l"(a), "l"(b), "l"(c)); return d;
}
__device__ __forceinline__ ull mul2(ull a, ull b) {
    ull d; asm("mul.rn.f32x2 %0, %1, %2;" : "=l"(d) : "l"(a), "l"(b)); return d;
}
__device__ __forceinline__ ull add2(ull a, ull b) {
    ull d; asm("add.rn.f32x2 %0, %1, %2;" : "=l"(d) : "l"(a), "l"(b)); return d;
}
// single-MUFU tanh (MUFU.TANH): ~6e-4 per-step error; recurrence contracts it
// (measured contraction ~0.05x with the ex2 variant) -> final ~1e-5.
__device__ __forceinline__ float tanh_hw(float z) {
    float r; asm("tanh.approx.f32 %0, %1;" : "=f"(r) : "f"(z)); return r;
}
__device__ __forceinline__ float sigmoid1(float z) {
    float e; asm("ex2.approx.f32 %0, %1;" : "=f"(e) : "f"(z * -1.4426950408889634f));
    float r; asm("rcp.approx.f32 %0, %1;" : "=f"(r) : "f"(e + 1.0f));
    return r;
}

// K-pair permutation (dot order-free):
//   j in [0,8): (5*(j>>1) + 2*(j&1), +1) -> thread q OWNS pairs 2q, 2q+1
//   j = 8: rows (4,9)   j = 9: rows (14,19)  (straddle pairs)
__device__ __forceinline__ int pairA(int j) {
    if (j == 8) return 4;
    if (j == 9) return 14;
    return 5 * (j >> 1) + 2 * (j & 1);
}
__device__ __forceinline__ int pairB(int j) {
    if (j == 8) return 9;
    if (j == 9) return 19;
    return 5 * (j >> 1) + 2 * (j & 1) + 1;
}

// 4 threads per batch (quad), TWO batches per thread (streams A/B) for ILP:
// streams share the 100 weight regs and hide each other's MUFU/LDS latency.
// Dot = two 5-deep fma2 chains + add2 combine (halved chain depth).
// tanh = single MUFU.TANH. Exchange via double-buffered smem per stream.
// Grid 1024 x 32thr (16 batches/block): ~190 regs -> >=8 blocks/SM >= 7
// needed -> SINGLE balanced wave. Bare bounds (caps spill: R4/R6).
__global__ void __launch_bounds__(32) rnn_kernel(
    const float* __restrict__ x,      // [B, TLEN]
    const float* __restrict__ W_ih,   // [H]
    const float* __restrict__ W_hh,   // [H, H]
    const float* __restrict__ b_ih,   // [H]
    const float* __restrict__ b_hh,   // [H]
    const float* __restrict__ W_fc,   // [H]
    const float* __restrict__ b_fc,   // [1]
    float* __restrict__ out)          // [B]
{
    __shared__ float sW[H][H];            // raw W_hh (no pre-scale needed now)
    __shared__ ull hbuf[2][2][10][8];     // [buf][stream][pair][batch8]
    __shared__ float sWih[H], sPre[H], sWfc[H];
    __shared__ float sBfc;

    const int tid = threadIdx.x;
    for (int i = tid; i < H * H; i += 32) sW[i / H][i % H] = W_hh[i];
    if (tid < H) {
        sWih[tid] = W_ih[tid];
        sPre[tid] = b_ih[tid] + b_hh[tid];
        sWfc[tid] = W_fc[tid];
    }
    if (tid == 0) sBfc = b_fc[0];
    __syncthreads();

    const int q  = tid & 3;
    const int b8 = tid >> 2;
    const int batchA = blockIdx.x * 16 + b8;
    const int batchB = batchA + 8;

    // shared register weights: rows 5q..5q+4, 10 permuted K-pairs each
    ull wk[5][10], pre2[5];
    float wih[5];
    #pragma unroll
    for (int i = 0; i < 5; i++) {
        const int r = 5 * q + i;
        #pragma unroll
        for (int j = 0; j < 10; j++)
            wk[i][j] = pk(sW[r][pairA(j)], sW[r][pairB(j)]);
        wih[i]  = sWih[r];
        pre2[i] = pk(sPre[r], 0.0f);
    }

    ull ha[10], hb[10];
    #pragma unroll
    for (int j = 0; j < 10; j++) { ha[j] = 0ull; hb[j] = 0ull; }

    const float* xpA = x + (size_t)batchA * TLEN;
    const float* xpB = x + (size_t)batchB * TLEN;

    for (int t = 0; t < TLEN; t += 4) {
        const float4 xva = *(const float4*)(xpA + t);
        const float4 xvb = *(const float4*)(xpB + t);
        const float xa[4] = {xva.x, xva.y, xva.z, xva.w};
        const float xb[4] = {xvb.x, xvb.y, xvb.z, xvb.w};

        #pragma unroll
        for (int s = 0; s < 4; s++) {
            const int buf = s & 1;
            float ma[5], mb[5];
            #pragma unroll
            for (int i = 0; i < 5; i++) {
                // stream A: two 5-deep chains
                ull aL = fma2(wk[i][0], ha[0], pre2[i]);
                ull aH = mul2(wk[i][5], ha[5]);
                // stream B
                ull bL = fma2(wk[i][0], hb[0], pre2[i]);
                ull bH = mul2(wk[i][5], hb[5]);
                #pragma unroll
                for (int j = 1; j < 5; j++) {
                    aL = fma2(wk[i][j], ha[j], aL);
                    aH = fma2(wk[i][5 + j], ha[5 + j], aH);
                    bL = fma2(wk[i][j], hb[j], bL);
                    bH = fma2(wk[i][5 + j], hb[5 + j], bH);
                }
                float2 fa = upk(add2(aL, aH));
                float2 fb = upk(add2(bL, bH));
                ma[i] = tanh_hw(fmaf(xa[s], wih[i], fa.x + fa.y));
                mb[i] = tanh_hw(fmaf(xb[s], wih[i], fb.x + fb.y));
            }
            // quad exchange, both streams, one syncwarp
            hbuf[buf][0][2 * q][b8]     = pk(ma[0], ma[1]);
            hbuf[buf][0][2 * q + 1][b8] = pk(ma[2], ma[3]);
            ((float*)&hbuf[buf][0][8 + (q >> 1)][b8])[q & 1] = ma[4];
            hbuf[buf][1][2 * q][b8]     = pk(mb[0], mb[1]);
            hbuf[buf][1][2 * q + 1][b8] = pk(mb[2], mb[3]);
            ((float*)&hbuf[buf][1][8 + (q >> 1)][b8])[q & 1] = mb[4];
            __syncwarp();
            #pragma unroll
            for (int j = 0; j < 10; j++) {
                ha[j] = hbuf[buf][0][j][b8];
                hb[j] = hbuf[buf][1][j][b8];
            }
        }
    }

    if (q == 0) {
        ull accA = pk(sBfc, 0.0f), accB = pk(sBfc, 0.0f);
        #pragma unroll
        for (int j = 0; j < 10; j++) {
            ull wf = pk(sWfc[pairA(j)], sWfc[pairB(j)]);
            accA = fma2(ha[j], wf, accA);
            accB = fma2(hb[j], wf, accB);
        }
        float2 fa = upk(accA), fb = upk(accB);
        out[batchA] = sigmoid1(fa.x + fa.y);
        out[batchB] = sigmoid1(fb.x + fb.y);
    }
}

extern "C" void kernel_launch(void* const* d_in, const int* in_sizes, int n_in,
                              void* d_out, int out_size) {
    const float* x    = (const float*)d_in[0];
    const float* W_ih = (const float*)d_in[1];
    const float* W_hh = (const float*)d_in[2];
    const float* b_ih = (const float*)d_in[3];
    const float* b_hh = (const float*)d_in[4];
    const float* W_fc = (const float*)d_in[5];
    const float* b_fc = (const float*)d_in[6];
    float* out = (float*)d_out;

    const int B = in_sizes[0] / TLEN;   // 16384
    const int blocks = B / 16;          // 1024 blocks x 32 threads, 2 batches/thread
    rnn_kernel<<<blocks, 32>>>(x, W_ih, W_hh, b_ih, b_hh, W_fc, b_fc, out);
}